// round 15
// baseline (speedup 1.0000x reference)
#include <cuda_runtime.h>
#include <cstdint>
#include <cstddef>
typedef unsigned long long ull; typedef ulonglong2 ull2;
#define DI __device__ __forceinline__

namespace {
constexpr int T = 512, OUTW = 24, CL = 8, Br = 16, NTHR = 128;
constexpr int H1S = 260, H2S = 130, XSS = 68;
constexpr int H1R = 15 * H1S + 256;          // 4156: trimmed region (row15 no tail)
constexpr int H2R = Br * H2S;                // 2080
constexpr int XSR = 15 * XSS + 64;           // 1084
constexpr int OFF_R1 = 8;
constexpr int OFF_K1 = OFF_R1 + 24576;
constexpr int OFF_K2 = OFF_K1 + 6144;
constexpr int OFF_R2 = OFF_K2 + 12288;
constexpr int OFF_H1 = OFF_R2 + 6144;        // 49160
constexpr int OFF_H2 = OFF_H1 + H1R;         // 53316
constexpr int OFF_XS = OFF_H2 + H2R;         // 55396
constexpr int OFF_SC = OFF_XS + XSR;         // 56480
constexpr int SMEM_FLOATS = OFF_SC + 1632;   // 58112
constexpr size_t SMEM_BYTES = SMEM_FLOATS * sizeof(float);  // 232448 == cap
}

DI float sigf(float v) { return __fdividef(1.f, 1.f + __expf(-v)); }
DI float tanhf_(float v) {
    float e = __expf(2.f * fabsf(v));
    return copysignf(1.f - __fdividef(2.f, e + 1.f), v);
}
DI void cl_sync() {
    asm volatile("barrier.cluster.arrive.aligned;" ::: "memory");
    asm volatile("barrier.cluster.wait.aligned;" ::: "memory");
}
DI uint32_t mapa_u32(uint32_t a, uint32_t r) {
    uint32_t p; asm("mapa.shared::cluster.u32 %0,%1,%2;" : "=r"(p) : "r"(a), "r"(r)); return p;
}
DI void st_rem64(uint32_t a, ull v) {
    asm volatile("st.shared::cluster.b64 [%0],%1;" :: "r"(a), "l"(v) : "memory");
}
DI ull pk2(float a, float b) { ull r; asm("mov.b64 %0,{%1,%2};" : "=l"(r) : "f"(a), "f"(b)); return r; }
DI float2 upk(ull v) { float2 r; asm("mov.b64 {%0,%1},%2;" : "=f"(r.x), "=f"(r.y) : "l"(v)); return r; }
DI void f2(ull& d, ull a, ull b) { asm("fma.rn.f32x2 %0,%1,%2,%0;" : "+l"(d) : "l"(a), "l"(b)); }
DI void a2(ull& d, ull b) { asm("add.rn.f32x2 %0,%0,%1;" : "+l"(d) : "l"(b)); }
DI void mb_init(uint32_t a, uint32_t n) {
    asm volatile("mbarrier.init.shared.b64 [%0],%1;" :: "r"(a), "r"(n) : "memory");
}
DI void mb_post(uint32_t la, uint32_t rk) {
    asm volatile("{ .reg .b32 ra;\n\t"
        "mapa.shared::cluster.u32 ra,%0,%1;\n\t"
        "mbarrier.arrive.release.cluster.shared::cluster.b64 _,[ra]; }"
        :: "r"(la), "r"(rk) : "memory");
}
DI void mb_wait(uint32_t a, uint32_t p) {
    asm volatile("{ .reg .pred P;\n"
        "W%=: mbarrier.try_wait.parity.acquire.cluster.shared::cta.b64 P,[%0],%1,0x989680;\n\t"
        "@P bra.uni D%=;\n\t"
        "bra.uni W%=;\n"
        "D%=: }" :: "r"(a), "r"(p) : "memory");
}

// GRU1 inner macro: one k with packed value pair (v0=row0, v1=row1)
#define G1_STEP(WP, kk, v0, v1, AH)                                             \
    {   ull2 wz = (WP)[(kk)*24 + ctA], wr = (WP)[(kk)*24 + 8 + ctA],            \
             wh = (WP)[(kk)*24 + 16 + ctA];                                     \
        f2(az[0][0], v0, wz.x); f2(az[0][1], v0, wz.y);                         \
        f2(az[1][0], v1, wz.x); f2(az[1][1], v1, wz.y);                         \
        f2(ar[0][0], v0, wr.x); f2(ar[0][1], v0, wr.y);                         \
        f2(ar[1][0], v1, wr.x); f2(ar[1][1], v1, wr.y);                         \
        f2((AH)[0][0], v0, wh.x); f2((AH)[0][1], v0, wh.y);                     \
        f2((AH)[1][0], v1, wh.x); f2((AH)[1][1], v1, wh.y); }

__global__ void __launch_bounds__(NTHR, 1) __cluster_dims__(CL, 1, 1)
gru_stack_kernel(const float* __restrict__ x,  const float* __restrict__ k1,
                 const float* __restrict__ r1, const float* __restrict__ b1,
                 const float* __restrict__ k2, const float* __restrict__ r2,
                 const float* __restrict__ b2, const float* __restrict__ w3,
                 const float* __restrict__ b3, const float* __restrict__ w4,
                 const float* __restrict__ b4, const float* __restrict__ w5,
                 const float* __restrict__ b5, float* __restrict__ out)
{
    extern __shared__ float sm[];
    const int tid = threadIdx.x;
    const int c = blockIdx.x & 7, g = blockIdx.x >> 3;

    uint32_t sb;
    asm("{ .reg .u64 t; cvta.to.shared.u64 t,%1; cvt.u32.u64 %0,t; }" : "=r"(sb) : "l"(sm));
    const uint32_t mFREE = sb, mRDY1 = sb + 8, mRDY2 = sb + 16;
    if (tid == 0) { mb_init(mFREE, 8); mb_init(mRDY1, 8); mb_init(mRDY2, 8); }

    for (int i = tid; i < 24576; i += NTHR) {
        int k = i / 96, j = i % 96;
        sm[OFF_R1 + i] = r1[k*768 + (j>>5)*256 + (c<<5) + (j&31)];
    }
    for (int i = tid; i < 6144; i += NTHR) {
        int k = i / 96, j = i % 96;
        sm[OFF_K1 + i] = k1[k*768 + (j>>5)*256 + (c<<5) + (j&31)];
    }
    for (int i = tid; i < 12288; i += NTHR) {
        int k = i / 48, j = i % 48;
        sm[OFF_K2 + i] = k2[k*384 + (j>>4)*128 + (c<<4) + (j&15)];
    }
    for (int i = tid; i < 6144; i += NTHR) {
        int k = i / 48, j = i % 48;
        sm[OFF_R2 + i] = r2[k*384 + (j>>4)*128 + (c<<4) + (j&15)];
    }
    for (int i = tid; i < H1R; i += NTHR) sm[OFF_H1 + i] = 0.f;
    for (int i = tid; i < H2R; i += NTHR) sm[OFF_H2 + i] = 0.f;
    for (int i = tid; i < Br*64; i += NTHR) {
        int r = i >> 6, f = i & 63;
        sm[OFF_XS + r*XSS + f] = x[((size_t)(g*Br + r)*T)*64 + f];
    }

    const int kcA = tid >> 6, rgA = (tid >> 3) & 7, ctA = tid & 7, rA0 = rgA*2;
    const int kcB = tid >> 5, rgB = (tid >> 2) & 7, ctB = tid & 3, rB0 = rgB*2;

    ull bzA[2], brA[2], bxA[2], bhA[2];
    if (kcA == 0) {
        #pragma unroll
        for (int p = 0; p < 2; p++) {
            int u0 = (c<<5) + ctA*4 + p*2, u1 = u0 + 1;
            bzA[p] = pk2(b1[u0]+b1[768+u0],      b1[u1]+b1[768+u1]);
            brA[p] = pk2(b1[256+u0]+b1[1024+u0], b1[256+u1]+b1[1024+u1]);
            bxA[p] = pk2(b1[512+u0],             b1[512+u1]);
            bhA[p] = pk2(b1[1280+u0],            b1[1280+u1]);
        }
    }
    ull bzB[2], brB[2], bxB[2], bhB[2];
    if (kcB == 0) {
        #pragma unroll
        for (int p = 0; p < 2; p++) {
            int u0 = (c<<4) + ctB*4 + p*2, u1 = u0 + 1;
            bzB[p] = pk2(b2[u0]+b2[384+u0],      b2[u1]+b2[384+u1]);
            brB[p] = pk2(b2[128+u0]+b2[512+u0],  b2[128+u1]+b2[512+u1]);
            bxB[p] = pk2(b2[256+u0],             b2[256+u1]);
            bhB[p] = pk2(b2[640+u0],             b2[640+u1]);
        }
    }

    uint32_t map1[CL], map2[CL];
    {
        uint32_t la1 = sb + (uint32_t)(OFF_H1 + rA0*H1S + (c<<5) + ctA*4)*4u;
        uint32_t la2 = sb + (uint32_t)(OFF_H2 + rB0*H2S + (c<<4) + ctB*4)*4u;
        #pragma unroll
        for (int rk = 0; rk < CL; rk++) { map1[rk] = mapa_u32(la1, rk); map2[rk] = mapa_u32(la2, rk); }
    }
    const ull2* R1p = (const ull2*)(sm + OFF_R1);
    const ull2* K1p = (const ull2*)(sm + OFF_K1);
    const ull2* K2p = (const ull2*)(sm + OFF_K2);
    const ull2* R2p = (const ull2*)(sm + OFF_R2);
    ull* scU = (ull*)(sm + OFF_SC);

    float hpr[2][4] = {{0,0,0,0},{0,0,0,0}};
    float hqr[2][4] = {{0,0,0,0},{0,0,0,0}};

    __syncthreads();
    cl_sync();

    for (int t = 0; t < T; t++) {
        const uint32_t par = (uint32_t)(t & 1);
        float4 xr[4];
        if (kcA == 1 && t + 1 < T) {
            #pragma unroll
            for (int j = 0; j < 4; j++) {
                int i = (tid - 64)*4 + j, r = i >> 4, f4 = i & 15;
                xr[j] = *(const float4*)(x + ((size_t)(g*Br + r)*T + t + 1)*64 + f4*4);
            }
        }

        // ---- GRU1 projections (float4 value loads) ----
        ull az[2][2], ar[2][2], ax[2][2], ah[2][2];
        #pragma unroll
        for (int rr = 0; rr < 2; rr++)
            #pragma unroll
            for (int p = 0; p < 2; p++) {
                az[rr][p] = (kcA == 0) ? bzA[p] : 0ull;
                ar[rr][p] = (kcA == 0) ? brA[p] : 0ull;
                ax[rr][p] = (kcA == 0) ? bxA[p] : 0ull;
                ah[rr][p] = (kcA == 0) ? bhA[p] : 0ull;
            }
        const float* h0 = sm + OFF_H1 + rA0*H1S;
        const float* h1r = h0 + H1S;
        if (kcA == 0) {
            const float* x0 = sm + OFF_XS + rA0*XSS;
            const float* x1 = x0 + XSS;
            #pragma unroll 4
            for (int k = 0; k < 64; k += 4) {
                float4 a0 = *(const float4*)(x0 + k);
                float4 a1 = *(const float4*)(x1 + k);
                { ull v0 = pk2(a0.x,a0.x), v1 = pk2(a1.x,a1.x); G1_STEP(K1p, k,   v0, v1, ax) }
                { ull v0 = pk2(a0.y,a0.y), v1 = pk2(a1.y,a1.y); G1_STEP(K1p, k+1, v0, v1, ax) }
                { ull v0 = pk2(a0.z,a0.z), v1 = pk2(a1.z,a1.z); G1_STEP(K1p, k+2, v0, v1, ax) }
                { ull v0 = pk2(a0.w,a0.w), v1 = pk2(a1.w,a1.w); G1_STEP(K1p, k+3, v0, v1, ax) }
            }
        }
        {
            const int kb = kcA ? 96 : 0, ke = kcA ? 256 : 96;
            #pragma unroll 4
            for (int k = kb; k < ke; k += 4) {
                float4 a0 = *(const float4*)(h0 + k);
                float4 a1 = *(const float4*)(h1r + k);
                { ull v0 = pk2(a0.x,a0.x), v1 = pk2(a1.x,a1.x); G1_STEP(R1p, k,   v0, v1, ah) }
                { ull v0 = pk2(a0.y,a0.y), v1 = pk2(a1.y,a1.y); G1_STEP(R1p, k+1, v0, v1, ah) }
                { ull v0 = pk2(a0.z,a0.z), v1 = pk2(a1.z,a1.z); G1_STEP(R1p, k+2, v0, v1, ah) }
                { ull v0 = pk2(a0.w,a0.w), v1 = pk2(a1.w,a1.w); G1_STEP(R1p, k+3, v0, v1, ah) }
            }
        }

        // ---- GRU2 recurrent proj ----
        if (t > 0) mb_wait(mRDY2, (uint32_t)((t - 1) & 1));
        ull bz[2][2], br_[2][2], bx[2][2], bh[2][2];
        #pragma unroll
        for (int rr = 0; rr < 2; rr++)
            #pragma unroll
            for (int p = 0; p < 2; p++) {
                bz[rr][p]  = (kcB == 0) ? bzB[p] : 0ull;
                br_[rr][p] = (kcB == 0) ? brB[p] : 0ull;
                bx[rr][p]  = (kcB == 0) ? bxB[p] : 0ull;
                bh[rr][p]  = (kcB == 0) ? bhB[p] : 0ull;
            }
        {
            const float* g0 = sm + OFF_H2 + rB0*H2S;
            const float* g1 = g0 + H2S;
            const int kb = kcB * 32;
            #pragma unroll 8
            for (int k = kb; k < kb + 32; k += 2) {
                float2 a0 = *(const float2*)(g0 + k);
                float2 a1 = *(const float2*)(g1 + k);
                #pragma unroll
                for (int s = 0; s < 2; s++) {
                    ull v0 = pk2(s ? a0.y : a0.x, s ? a0.y : a0.x);
                    ull v1 = pk2(s ? a1.y : a1.x, s ? a1.y : a1.x);
                    int kk = k + s;
                    ull2 wz = R2p[kk*12+ctB], wr = R2p[kk*12+4+ctB], wh = R2p[kk*12+8+ctB];
                    f2(bz[0][0], v0, wz.x); f2(bz[0][1], v0, wz.y);
                    f2(bz[1][0], v1, wz.x); f2(bz[1][1], v1, wz.y);
                    f2(br_[0][0], v0, wr.x); f2(br_[0][1], v0, wr.y);
                    f2(br_[1][0], v1, wr.x); f2(br_[1][1], v1, wr.y);
                    f2(bh[0][0], v0, wh.x); f2(bh[0][1], v0, wh.y);
                    f2(bh[1][0], v1, wh.x); f2(bh[1][1], v1, wh.y);
                }
            }
        }
        __syncthreads();                       // S1
        if (tid < 8) mb_post(mFREE, (uint32_t)tid);

        if (kcA == 1) {
            #pragma unroll
            for (int rr = 0; rr < 2; rr++) {
                int r = rA0 + rr;
                #pragma unroll
                for (int p = 0; p < 2; p++) {
                    scU[r*50 +      ctA*2 + p] = az[rr][p];
                    scU[r*50 + 16 + ctA*2 + p] = ar[rr][p];
                    scU[r*50 + 32 + ctA*2 + p] = ah[rr][p];
                }
            }
            if (t + 1 < T) {
                #pragma unroll
                for (int j = 0; j < 4; j++) {
                    int i = (tid - 64)*4 + j, r = i >> 4, f4 = i & 15;
                    *(float4*)(sm + OFF_XS + r*XSS + f4*4) = xr[j];
                }
            }
        }
        __syncthreads();                       // S2
        if (kcA == 0) {
            float hn1[2][4];
            #pragma unroll
            for (int rr = 0; rr < 2; rr++) {
                int r = rA0 + rr;
                #pragma unroll
                for (int p = 0; p < 2; p++) {
                    a2(az[rr][p], scU[r*50 +      ctA*2 + p]);
                    a2(ar[rr][p], scU[r*50 + 16 + ctA*2 + p]);
                    a2(ah[rr][p], scU[r*50 + 32 + ctA*2 + p]);
                    float2 vz = upk(az[rr][p]), vr = upk(ar[rr][p]);
                    float2 vx = upk(ax[rr][p]), vh = upk(ah[rr][p]);
                    float z0 = sigf(vz.x), r0 = sigf(vr.x);
                    float hh0 = tanhf_(vx.x + r0*vh.x);
                    float z1 = sigf(vz.y), r1g = sigf(vr.y);
                    float hh1 = tanhf_(vx.y + r1g*vh.y);
                    hn1[rr][p*2]   = z0*hpr[rr][p*2]   + (1.f - z0)*hh0;
                    hn1[rr][p*2+1] = z1*hpr[rr][p*2+1] + (1.f - z1)*hh1;
                }
            }
            #pragma unroll
            for (int rr = 0; rr < 2; rr++)
                #pragma unroll
                for (int i = 0; i < 4; i++) hpr[rr][i] = hn1[rr][i];
            mb_wait(mFREE, par);
            ull q00 = pk2(hn1[0][0], hn1[0][1]), q01 = pk2(hn1[0][2], hn1[0][3]);
            ull q10 = pk2(hn1[1][0], hn1[1][1]), q11 = pk2(hn1[1][2], hn1[1][3]);
            #pragma unroll
            for (int rk = 0; rk < CL; rk++) {
                uint32_t p0 = map1[rk];
                st_rem64(p0, q00); st_rem64(p0 + 8, q01);
                uint32_t p1 = p0 + (uint32_t)(H1S*4);
                st_rem64(p1, q10); st_rem64(p1 + 8, q11);
            }
            asm volatile("bar.sync 1,64;" ::: "memory");
            if (tid < 8) mb_post(mRDY1, (uint32_t)tid);
        }
        mb_wait(mRDY1, par);                   // h1(t) visible

        // ---- GRU2 input proj (h1(t) @ k2) ----
        {
            const float* g0 = sm + OFF_H1 + rB0*H1S;
            const float* g1 = g0 + H1S;
            const int kb = kcB * 64;
            #pragma unroll 8
            for (int k = kb; k < kb + 64; k += 2) {
                float2 a0 = *(const float2*)(g0 + k);
                float2 a1 = *(const float2*)(g1 + k);
                #pragma unroll
                for (int s = 0; s < 2; s++) {
                    ull v0 = pk2(s ? a0.y : a0.x, s ? a0.y : a0.x);
                    ull v1 = pk2(s ? a1.y : a1.x, s ? a1.y : a1.x);
                    int kk = k + s;
                    ull2 wz = K2p[kk*12+ctB], wr = K2p[kk*12+4+ctB], wh = K2p[kk*12+8+ctB];
                    f2(bz[0][0], v0, wz.x); f2(bz[0][1], v0, wz.y);
                    f2(bz[1][0], v1, wz.x); f2(bz[1][1], v1, wz.y);
                    f2(br_[0][0], v0, wr.x); f2(br_[0][1], v0, wr.y);
                    f2(br_[1][0], v1, wr.x); f2(br_[1][1], v1, wr.y);
                    f2(bx[0][0], v0, wh.x); f2(bx[0][1], v0, wh.y);
                    f2(bx[1][0], v1, wh.x); f2(bx[1][1], v1, wh.y);
                }
            }
        }
        __syncthreads();                       // S3
        if (kcB > 0) {
            int m = kcB - 1;
            #pragma unroll
            for (int rr = 0; rr < 2; rr++) {
                int r = rB0 + rr;
                #pragma unroll
                for (int p = 0; p < 2; p++) {
                    scU[m*272 + r*17 +     ctB*2 + p] = bz[rr][p];
                    scU[m*272 + r*17 + 8 + ctB*2 + p] = br_[rr][p];
                }
            }
        }
        __syncthreads();                       // S4
        if (kcB == 0) {
            #pragma unroll
            for (int m = 0; m < 3; m++)
                #pragma unroll
                for (int rr = 0; rr < 2; rr++) {
                    int r = rB0 + rr;
                    #pragma unroll
                    for (int p = 0; p < 2; p++) {
                        a2(bz[rr][p],  scU[m*272 + r*17 +     ctB*2 + p]);
                        a2(br_[rr][p], scU[m*272 + r*17 + 8 + ctB*2 + p]);
                    }
                }
        }
        __syncthreads();                       // S5
        if (kcB > 0) {
            int m = kcB - 1;
            #pragma unroll
            for (int rr = 0; rr < 2; rr++) {
                int r = rB0 + rr;
                #pragma unroll
                for (int p = 0; p < 2; p++) {
                    scU[m*272 + r*17 +     ctB*2 + p] = bx[rr][p];
                    scU[m*272 + r*17 + 8 + ctB*2 + p] = bh[rr][p];
                }
            }
        }
        __syncthreads();                       // S6
        if (kcB == 0) {
            float hn2[2][4];
            #pragma unroll
            for (int rr = 0; rr < 2; rr++) {
                int r = rB0 + rr;
                #pragma unroll
                for (int p = 0; p < 2; p++) {
                    #pragma unroll
                    for (int m = 0; m < 3; m++) {
                        a2(bx[rr][p], scU[m*272 + r*17 +     ctB*2 + p]);
                        a2(bh[rr][p], scU[m*272 + r*17 + 8 + ctB*2 + p]);
                    }
                    float2 vz = upk(bz[rr][p]), vr = upk(br_[rr][p]);
                    float2 vx = upk(bx[rr][p]), vh = upk(bh[rr][p]);
                    float z0 = sigf(vz.x), r0 = sigf(vr.x);
                    float hh0 = tanhf_(vx.x + r0*vh.x);
                    float z1 = sigf(vz.y), r1g = sigf(vr.y);
                    float hh1 = tanhf_(vx.y + r1g*vh.y);
                    hn2[rr][p*2]   = z0*hqr[rr][p*2]   + (1.f - z0)*hh0;
                    hn2[rr][p*2+1] = z1*hqr[rr][p*2+1] + (1.f - z1)*hh1;
                }
            }
            #pragma unroll
            for (int rr = 0; rr < 2; rr++)
                #pragma unroll
                for (int i = 0; i < 4; i++) hqr[rr][i] = hn2[rr][i];
            mb_wait(mFREE, par);
            ull q00 = pk2(hn2[0][0], hn2[0][1]), q01 = pk2(hn2[0][2], hn2[0][3]);
            ull q10 = pk2(hn2[1][0], hn2[1][1]), q11 = pk2(hn2[1][2], hn2[1][3]);
            #pragma unroll
            for (int rk = 0; rk < CL; rk++) {
                uint32_t p0 = map2[rk];
                st_rem64(p0, q00); st_rem64(p0 + 8, q01);
                uint32_t p1 = p0 + (uint32_t)(H2S*4);
                st_rem64(p1, q10); st_rem64(p1 + 8, q11);
            }
            __syncwarp();
            if (tid < 8) mb_post(mRDY2, (uint32_t)tid);
        }
    }
    mb_wait(mRDY2, (uint32_t)((T - 1) & 1));

    if (c == 0) {
        float* sD3 = sm + OFF_SC;
        float* sD4 = sm + OFF_SC + Br*64;
        __syncthreads();
        for (int i = tid; i < Br*64; i += NTHR) {
            int r = i >> 6, o = i & 63;
            float a = b3[o];
            #pragma unroll 8
            for (int k = 0; k < 128; k++) a += sm[OFF_H2 + r*H2S + k] * w3[k*64 + o];
            sD3[i] = a;
        }
        __syncthreads();
        for (int i = tid; i < Br*32; i += NTHR) {
            int r = i >> 5, o = i & 31;
            float a = b4[o];
            #pragma unroll 8
            for (int k = 0; k < 64; k++) a += sD3[r*64 + k] * w4[k*32 + o];
            sD4[i] = a;
        }
        __syncthreads();
        for (int i = tid; i < Br*OUTW; i += NTHR) {
            int r = i / OUTW, o = i % OUTW;
            float a = b5[o];
            #pragma unroll 8
            for (int k = 0; k < 32; k++) a += sD4[r*32 + k] * w5[k*OUTW + o];
            out[(g*Br + r)*OUTW + o] = a;
        }
    }
}

extern "C" void kernel_launch(void* const* d_in, const int* in_sizes, int n_in,
                              void* d_out, int out_size) {
    (void)in_sizes; (void)n_in; (void)out_size;
    const float* x  = (const float*)d_in[0];
    const float* k1 = (const float*)d_in[1];
    const float* r1 = (const float*)d_in[2];
    const float* b1 = (const float*)d_in[3];
    const float* k2 = (const float*)d_in[4];
    const float* r2 = (const float*)d_in[5];
    const float* b2 = (const float*)d_in[6];
    const float* w3 = (const float*)d_in[7];
    const float* b3 = (const float*)d_in[8];
    const float* w4 = (const float*)d_in[9];
    const float* b4 = (const float*)d_in[10];
    const float* w5 = (const float*)d_in[11];
    const float* b5 = (const float*)d_in[12];
    float* out = (float*)d_out;
    cudaFuncSetAttribute(gru_stack_kernel,
                         cudaFuncAttributeMaxDynamicSharedMemorySize, (int)SMEM_BYTES);
    gru_stack_kernel<<<128, NTHR, SMEM_BYTES>>>(
        x, k1, r1, b1, k2, r2, b2, w3, b3, w4, b4, w5, b5, out);
}

// round 16
// speedup vs baseline: 1.0323x; 1.0323x over previous
#include <cuda_runtime.h>
#include <cstdint>
#include <cstddef>
typedef unsigned long long ull; typedef ulonglong2 ull2;
#define DI __device__ __forceinline__

namespace {
constexpr int T = 512, OUTW = 24, CL = 8, Br = 16, NTHR = 128;
constexpr int H1S = 258, H2S = 130, XSS = 68;
constexpr int OFF_R1 = 8;
constexpr int OFF_K1 = OFF_R1 + 24576;
constexpr int OFF_K2 = OFF_K1 + 6144;
constexpr int OFF_R2 = OFF_K2 + 12288;
constexpr int OFF_H1 = OFF_R2 + 6144;
constexpr int OFF_H2 = OFF_H1 + Br * H1S;
constexpr int OFF_XS = OFF_H2 + Br * H2S;
constexpr int OFF_SC = OFF_XS + Br * XSS;
constexpr int SMEM_FLOATS = OFF_SC + 1632;
constexpr size_t SMEM_BYTES = SMEM_FLOATS * sizeof(float);  // 232352 <= 232448
}

DI float sigf(float v) { return __fdividef(1.f, 1.f + __expf(-v)); }
DI float tanhf_(float v) {
    float e = __expf(2.f * fabsf(v));
    return copysignf(1.f - __fdividef(2.f, e + 1.f), v);
}
DI void cl_sync() {
    asm volatile("barrier.cluster.arrive.aligned;" ::: "memory");
    asm volatile("barrier.cluster.wait.aligned;" ::: "memory");
}
DI uint32_t mapa_u32(uint32_t a, uint32_t r) {
    uint32_t p; asm("mapa.shared::cluster.u32 %0,%1,%2;" : "=r"(p) : "r"(a), "r"(r)); return p;
}
DI void st_rem64(uint32_t a, ull v) {
    asm volatile("st.shared::cluster.b64 [%0],%1;" :: "r"(a), "l"(v) : "memory");
}
DI ull pk2(float a, float b) { ull r; asm("mov.b64 %0,{%1,%2};" : "=l"(r) : "f"(a), "f"(b)); return r; }
DI float2 upk(ull v) { float2 r; asm("mov.b64 {%0,%1},%2;" : "=f"(r.x), "=f"(r.y) : "l"(v)); return r; }
DI void f2(ull& d, ull a, ull b) { asm("fma.rn.f32x2 %0,%1,%2,%0;" : "+l"(d) : "l"(a), "l"(b)); }
DI void a2(ull& d, ull b) { asm("add.rn.f32x2 %0,%0,%1;" : "+l"(d) : "l"(b)); }
DI void mb_init(uint32_t a, uint32_t n) {
    asm volatile("mbarrier.init.shared.b64 [%0],%1;" :: "r"(a), "r"(n) : "memory");
}
DI void mb_post(uint32_t la, uint32_t rk) {
    asm volatile("{ .reg .b32 ra;\n\t"
        "mapa.shared::cluster.u32 ra,%0,%1;\n\t"
        "mbarrier.arrive.release.cluster.shared::cluster.b64 _,[ra]; }"
        :: "r"(la), "r"(rk) : "memory");
}
DI void mb_wait(uint32_t a, uint32_t p) {
    asm volatile("{ .reg .pred P;\n"
        "W%=: mbarrier.try_wait.parity.acquire.cluster.shared::cta.b64 P,[%0],%1,0x989680;\n\t"
        "@P bra.uni D%=;\n\t"
        "bra.uni W%=;\n"
        "D%=: }" :: "r"(a), "r"(p) : "memory");
}

__global__ void __launch_bounds__(NTHR, 1) __cluster_dims__(CL, 1, 1)
gru_stack_kernel(const float* __restrict__ x,  const float* __restrict__ k1,
                 const float* __restrict__ r1, const float* __restrict__ b1,
                 const float* __restrict__ k2, const float* __restrict__ r2,
                 const float* __restrict__ b2, const float* __restrict__ w3,
                 const float* __restrict__ b3, const float* __restrict__ w4,
                 const float* __restrict__ b4, const float* __restrict__ w5,
                 const float* __restrict__ b5, float* __restrict__ out)
{
    extern __shared__ float sm[];
    const int tid = threadIdx.x;
    const int c = blockIdx.x & 7, g = blockIdx.x >> 3;

    uint32_t sb;
    asm("{ .reg .u64 t; cvta.to.shared.u64 t,%1; cvt.u32.u64 %0,t; }" : "=r"(sb) : "l"(sm));
    const uint32_t mFREE = sb, mRDY1 = sb + 8, mRDY2 = sb + 16;
    if (tid == 0) { mb_init(mFREE, 8); mb_init(mRDY1, 8); mb_init(mRDY2, 8); }

    for (int i = tid; i < 24576; i += NTHR) {
        int k = i / 96, j = i % 96;
        sm[OFF_R1 + i] = r1[k*768 + (j>>5)*256 + (c<<5) + (j&31)];
    }
    for (int i = tid; i < 6144; i += NTHR) {
        int k = i / 96, j = i % 96;
        sm[OFF_K1 + i] = k1[k*768 + (j>>5)*256 + (c<<5) + (j&31)];
    }
    for (int i = tid; i < 12288; i += NTHR) {
        int k = i / 48, j = i % 48;
        sm[OFF_K2 + i] = k2[k*384 + (j>>4)*128 + (c<<4) + (j&15)];
    }
    for (int i = tid; i < 6144; i += NTHR) {
        int k = i / 48, j = i % 48;
        sm[OFF_R2 + i] = r2[k*384 + (j>>4)*128 + (c<<4) + (j&15)];
    }
    for (int i = tid; i < Br*H1S; i += NTHR) sm[OFF_H1 + i] = 0.f;
    for (int i = tid; i < Br*H2S; i += NTHR) sm[OFF_H2 + i] = 0.f;
    for (int i = tid; i < Br*64; i += NTHR) {
        int r = i >> 6, f = i & 63;
        sm[OFF_XS + r*XSS + f] = x[((size_t)(g*Br + r)*T)*64 + f];
    }

    const int kcA = tid >> 6, rgA = (tid >> 3) & 7, ctA = tid & 7, rA0 = rgA*2;
    const int kcB = tid >> 5, rgB = (tid >> 2) & 7, ctB = tid & 3, rB0 = rgB*2;

    ull bzA[2], brA[2], bxA[2], bhA[2];
    if (kcA == 0) {
        #pragma unroll
        for (int p = 0; p < 2; p++) {
            int u0 = (c<<5) + ctA*4 + p*2, u1 = u0 + 1;
            bzA[p] = pk2(b1[u0]+b1[768+u0],      b1[u1]+b1[768+u1]);
            brA[p] = pk2(b1[256+u0]+b1[1024+u0], b1[256+u1]+b1[1024+u1]);
            bxA[p] = pk2(b1[512+u0],             b1[512+u1]);
            bhA[p] = pk2(b1[1280+u0],            b1[1280+u1]);
        }
    }
    ull bzB[2], brB[2], bxB[2], bhB[2];
    if (kcB == 0) {
        #pragma unroll
        for (int p = 0; p < 2; p++) {
            int u0 = (c<<4) + ctB*4 + p*2, u1 = u0 + 1;
            bzB[p] = pk2(b2[u0]+b2[384+u0],      b2[u1]+b2[384+u1]);
            brB[p] = pk2(b2[128+u0]+b2[512+u0],  b2[128+u1]+b2[512+u1]);
            bxB[p] = pk2(b2[256+u0],             b2[256+u1]);
            bhB[p] = pk2(b2[640+u0],             b2[640+u1]);
        }
    }

    uint32_t map1[CL], map2[CL];
    {
        uint32_t la1 = sb + (uint32_t)(OFF_H1 + rA0*H1S + (c<<5) + ctA*4)*4u;
        uint32_t la2 = sb + (uint32_t)(OFF_H2 + rB0*H2S + (c<<4) + ctB*4)*4u;
        #pragma unroll
        for (int rk = 0; rk < CL; rk++) { map1[rk] = mapa_u32(la1, rk); map2[rk] = mapa_u32(la2, rk); }
    }
    const ull2* R1p = (const ull2*)(sm + OFF_R1);
    const ull2* K1p = (const ull2*)(sm + OFF_K1);
    const ull2* K2p = (const ull2*)(sm + OFF_K2);
    const ull2* R2p = (const ull2*)(sm + OFF_R2);
    ull* scU = (ull*)(sm + OFF_SC);

    float hpr[2][4] = {{0,0,0,0},{0,0,0,0}};
    float hqr[2][4] = {{0,0,0,0},{0,0,0,0}};

    __syncthreads();
    cl_sync();

    for (int t = 0; t < T; t++) {
        const uint32_t par = (uint32_t)(t & 1);
        float4 xr[4];
        if (kcA == 1 && t + 1 < T) {
            #pragma unroll
            for (int j = 0; j < 4; j++) {
                int i = (tid - 64)*4 + j, r = i >> 4, f4 = i & 15;
                xr[j] = *(const float4*)(x + ((size_t)(g*Br + r)*T + t + 1)*64 + f4*4);
            }
        }

        // ---- GRU1 projections ----
        ull az[2][2], ar[2][2], ax[2][2], ah[2][2];
        #pragma unroll
        for (int rr = 0; rr < 2; rr++)
            #pragma unroll
            for (int p = 0; p < 2; p++) {
                az[rr][p] = (kcA == 0) ? bzA[p] : 0ull;
                ar[rr][p] = (kcA == 0) ? brA[p] : 0ull;
                ax[rr][p] = (kcA == 0) ? bxA[p] : 0ull;
                ah[rr][p] = (kcA == 0) ? bhA[p] : 0ull;
            }
        const float* h0 = sm + OFF_H1 + rA0*H1S;
        const float* h1r = h0 + H1S;
        if (kcA == 0) {
            const float* x0 = sm + OFF_XS + rA0*XSS;
            const float* x1 = x0 + XSS;
            #pragma unroll 4
            for (int k = 0; k < 64; k += 2) {
                float2 a0 = *(const float2*)(x0 + k);
                float2 a1 = *(const float2*)(x1 + k);
                #pragma unroll
                for (int s = 0; s < 2; s++) {
                    ull v0 = pk2(s ? a0.y : a0.x, s ? a0.y : a0.x);
                    ull v1 = pk2(s ? a1.y : a1.x, s ? a1.y : a1.x);
                    int kk = k + s;
                    ull2 wz = K1p[kk*24+ctA], wr = K1p[kk*24+8+ctA], wh = K1p[kk*24+16+ctA];
                    f2(az[0][0], v0, wz.x); f2(az[0][1], v0, wz.y);
                    f2(az[1][0], v1, wz.x); f2(az[1][1], v1, wz.y);
                    f2(ar[0][0], v0, wr.x); f2(ar[0][1], v0, wr.y);
                    f2(ar[1][0], v1, wr.x); f2(ar[1][1], v1, wr.y);
                    f2(ax[0][0], v0, wh.x); f2(ax[0][1], v0, wh.y);
                    f2(ax[1][0], v1, wh.x); f2(ax[1][1], v1, wh.y);
                }
            }
        }
        {   // GRU1 recurrent, main chunk: kc0 k in [32,96), kc1 k in [96,224)
            const int kb = kcA ? 96 : 32, ke = kcA ? 224 : 96;
            #pragma unroll 4
            for (int k = kb; k < ke; k += 2) {
                float2 a0 = *(const float2*)(h0 + k);
                float2 a1 = *(const float2*)(h1r + k);
                #pragma unroll
                for (int s = 0; s < 2; s++) {
                    ull v0 = pk2(s ? a0.y : a0.x, s ? a0.y : a0.x);
                    ull v1 = pk2(s ? a1.y : a1.x, s ? a1.y : a1.x);
                    int kk = k + s;
                    ull2 wz = R1p[kk*24+ctA], wr = R1p[kk*24+8+ctA], wh = R1p[kk*24+16+ctA];
                    f2(az[0][0], v0, wz.x); f2(az[0][1], v0, wz.y);
                    f2(az[1][0], v1, wz.x); f2(az[1][1], v1, wz.y);
                    f2(ar[0][0], v0, wr.x); f2(ar[0][1], v0, wr.y);
                    f2(ar[1][0], v1, wr.x); f2(ar[1][1], v1, wr.y);
                    f2(ah[0][0], v0, wh.x); f2(ah[0][1], v0, wh.y);
                    f2(ah[1][0], v1, wh.x); f2(ah[1][1], v1, wh.y);
                }
            }
        }

        // ---- wait h2(t-1), then FUSED: GRU1-h remainder + GRU2 recurrent ----
        if (t > 0) mb_wait(mRDY2, (uint32_t)((t - 1) & 1));
        ull bz[2][2], br_[2][2], bx[2][2], bh[2][2];
        #pragma unroll
        for (int rr = 0; rr < 2; rr++)
            #pragma unroll
            for (int p = 0; p < 2; p++) {
                bz[rr][p]  = (kcB == 0) ? bzB[p] : 0ull;
                br_[rr][p] = (kcB == 0) ? brB[p] : 0ull;
                bx[rr][p]  = (kcB == 0) ? bxB[p] : 0ull;
                bh[rr][p]  = (kcB == 0) ? bhB[p] : 0ull;
            }
        {
            const int kb1 = kcA ? 224 : 0;     // GRU1-h remainder (32 iters)
            const int kb2 = kcB * 32;          // GRU2-rec (32 iters)
            const float* g0 = sm + OFF_H2 + rB0*H2S;
            const float* g1 = g0 + H2S;
            #pragma unroll 4
            for (int j = 0; j < 32; j += 2) {
                // GRU1 part
                float2 a0 = *(const float2*)(h0 + kb1 + j);
                float2 a1 = *(const float2*)(h1r + kb1 + j);
                // GRU2 part
                float2 c0 = *(const float2*)(g0 + kb2 + j);
                float2 c1 = *(const float2*)(g1 + kb2 + j);
                #pragma unroll
                for (int s = 0; s < 2; s++) {
                    int k1i = kb1 + j + s;
                    ull v0 = pk2(s ? a0.y : a0.x, s ? a0.y : a0.x);
                    ull v1 = pk2(s ? a1.y : a1.x, s ? a1.y : a1.x);
                    ull2 wz = R1p[k1i*24+ctA], wr = R1p[k1i*24+8+ctA], wh = R1p[k1i*24+16+ctA];
                    f2(az[0][0], v0, wz.x); f2(az[0][1], v0, wz.y);
                    f2(az[1][0], v1, wz.x); f2(az[1][1], v1, wz.y);
                    f2(ar[0][0], v0, wr.x); f2(ar[0][1], v0, wr.y);
                    f2(ar[1][0], v1, wr.x); f2(ar[1][1], v1, wr.y);
                    f2(ah[0][0], v0, wh.x); f2(ah[0][1], v0, wh.y);
                    f2(ah[1][0], v1, wh.x); f2(ah[1][1], v1, wh.y);

                    int k2i = kb2 + j + s;
                    ull u0 = pk2(s ? c0.y : c0.x, s ? c0.y : c0.x);
                    ull u1 = pk2(s ? c1.y : c1.x, s ? c1.y : c1.x);
                    ull2 qz = R2p[k2i*12+ctB], qr = R2p[k2i*12+4+ctB], qh = R2p[k2i*12+8+ctB];
                    f2(bz[0][0], u0, qz.x); f2(bz[0][1], u0, qz.y);
                    f2(bz[1][0], u1, qz.x); f2(bz[1][1], u1, qz.y);
                    f2(br_[0][0], u0, qr.x); f2(br_[0][1], u0, qr.y);
                    f2(br_[1][0], u1, qr.x); f2(br_[1][1], u1, qr.y);
                    f2(bh[0][0], u0, qh.x); f2(bh[0][1], u0, qh.y);
                    f2(bh[1][0], u1, qh.x); f2(bh[1][1], u1, qh.y);
                }
            }
        }
        __syncthreads();                       // S1
        if (tid < 8) mb_post(mFREE, (uint32_t)tid);

        if (kcA == 1) {
            #pragma unroll
            for (int rr = 0; rr < 2; rr++) {
                int r = rA0 + rr;
                #pragma unroll
                for (int p = 0; p < 2; p++) {
                    scU[r*50 +      ctA*2 + p] = az[rr][p];
                    scU[r*50 + 16 + ctA*2 + p] = ar[rr][p];
                    scU[r*50 + 32 + ctA*2 + p] = ah[rr][p];
                }
            }
            if (t + 1 < T) {
                #pragma unroll
                for (int j = 0; j < 4; j++) {
                    int i = (tid - 64)*4 + j, r = i >> 4, f4 = i & 15;
                    *(float4*)(sm + OFF_XS + r*XSS + f4*4) = xr[j];
                }
            }
        }
        __syncthreads();                       // S2
        if (kcA == 0) {
            float hn1[2][4];
            #pragma unroll
            for (int rr = 0; rr < 2; rr++) {
                int r = rA0 + rr;
                #pragma unroll
                for (int p = 0; p < 2; p++) {
                    a2(az[rr][p], scU[r*50 +      ctA*2 + p]);
                    a2(ar[rr][p], scU[r*50 + 16 + ctA*2 + p]);
                    a2(ah[rr][p], scU[r*50 + 32 + ctA*2 + p]);
                    float2 vz = upk(az[rr][p]), vr = upk(ar[rr][p]);
                    float2 vx = upk(ax[rr][p]), vh = upk(ah[rr][p]);
                    float z0 = sigf(vz.x), r0 = sigf(vr.x);
                    float hh0 = tanhf_(vx.x + r0*vh.x);
                    float z1 = sigf(vz.y), r1g = sigf(vr.y);
                    float hh1 = tanhf_(vx.y + r1g*vh.y);
                    hn1[rr][p*2]   = z0*hpr[rr][p*2]   + (1.f - z0)*hh0;
                    hn1[rr][p*2+1] = z1*hpr[rr][p*2+1] + (1.f - z1)*hh1;
                }
            }
            #pragma unroll
            for (int rr = 0; rr < 2; rr++)
                #pragma unroll
                for (int i = 0; i < 4; i++) hpr[rr][i] = hn1[rr][i];
            mb_wait(mFREE, par);
            ull q00 = pk2(hn1[0][0], hn1[0][1]), q01 = pk2(hn1[0][2], hn1[0][3]);
            ull q10 = pk2(hn1[1][0], hn1[1][1]), q11 = pk2(hn1[1][2], hn1[1][3]);
            #pragma unroll
            for (int rk = 0; rk < CL; rk++) {
                uint32_t p0 = map1[rk];
                st_rem64(p0, q00); st_rem64(p0 + 8, q01);
                uint32_t p1 = p0 + (uint32_t)(H1S*4);
                st_rem64(p1, q10); st_rem64(p1 + 8, q11);
            }
            asm volatile("bar.sync 1,64;" ::: "memory");
            if (tid < 8) mb_post(mRDY1, (uint32_t)tid);
        }
        mb_wait(mRDY1, par);                   // h1(t) visible

        // ---- GRU2 input proj (h1(t) @ k2) ----
        {
            const float* g0 = sm + OFF_H1 + rB0*H1S;
            const float* g1 = g0 + H1S;
            const int kb = kcB * 64;
            #pragma unroll 4
            for (int k = kb; k < kb + 64; k += 2) {
                float2 a0 = *(const float2*)(g0 + k);
                float2 a1 = *(const float2*)(g1 + k);
                #pragma unroll
                for (int s = 0; s < 2; s++) {
                    ull v0 = pk2(s ? a0.y : a0.x, s ? a0.y : a0.x);
                    ull v1 = pk2(s ? a1.y : a1.x, s ? a1.y : a1.x);
                    int kk = k + s;
                    ull2 wz = K2p[kk*12+ctB], wr = K2p[kk*12+4+ctB], wh = K2p[kk*12+8+ctB];
                    f2(bz[0][0], v0, wz.x); f2(bz[0][1], v0, wz.y);
                    f2(bz[1][0], v1, wz.x); f2(bz[1][1], v1, wz.y);
                    f2(br_[0][0], v0, wr.x); f2(br_[0][1], v0, wr.y);
                    f2(br_[1][0], v1, wr.x); f2(br_[1][1], v1, wr.y);
                    f2(bx[0][0], v0, wh.x); f2(bx[0][1], v0, wh.y);
                    f2(bx[1][0], v1, wh.x); f2(bx[1][1], v1, wh.y);
                }
            }
        }
        __syncthreads();                       // S3
        if (kcB > 0) {
            int m = kcB - 1;
            #pragma unroll
            for (int rr = 0; rr < 2; rr++) {
                int r = rB0 + rr;
                #pragma unroll
                for (int p = 0; p < 2; p++) {
                    scU[m*272 + r*17 +     ctB*2 + p] = bz[rr][p];
                    scU[m*272 + r*17 + 8 + ctB*2 + p] = br_[rr][p];
                }
            }
        }
        __syncthreads();                       // S4
        if (kcB == 0) {
            #pragma unroll
            for (int m = 0; m < 3; m++)
                #pragma unroll
                for (int rr = 0; rr < 2; rr++) {
                    int r = rB0 + rr;
                    #pragma unroll
                    for (int p = 0; p < 2; p++) {
                        a2(bz[rr][p],  scU[m*272 + r*17 +     ctB*2 + p]);
                        a2(br_[rr][p], scU[m*272 + r*17 + 8 + ctB*2 + p]);
                    }
                }
        }
        __syncthreads();                       // S5
        if (kcB > 0) {
            int m = kcB - 1;
            #pragma unroll
            for (int rr = 0; rr < 2; rr++) {
                int r = rB0 + rr;
                #pragma unroll
                for (int p = 0; p < 2; p++) {
                    scU[m*272 + r*17 +     ctB*2 + p] = bx[rr][p];
                    scU[m*272 + r*17 + 8 + ctB*2 + p] = bh[rr][p];
                }
            }
        }
        __syncthreads();                       // S6
        if (kcB == 0) {
            float hn2[2][4];
            #pragma unroll
            for (int rr = 0; rr < 2; rr++) {
                int r = rB0 + rr;
                #pragma unroll
                for (int p = 0; p < 2; p++) {
                    #pragma unroll
                    for (int m = 0; m < 3; m++) {
                        a2(bx[rr][p], scU[m*272 + r*17 +     ctB*2 + p]);
                        a2(bh[rr][p], scU[m*272 + r*17 + 8 + ctB*2 + p]);
                    }
                    float2 vz = upk(bz[rr][p]), vr = upk(br_[rr][p]);
                    float2 vx = upk(bx[rr][p]), vh = upk(bh[rr][p]);
                    float z0 = sigf(vz.x), r0 = sigf(vr.x);
                    float hh0 = tanhf_(vx.x + r0*vh.x);
                    float z1 = sigf(vz.y), r1g = sigf(vr.y);
                    float hh1 = tanhf_(vx.y + r1g*vh.y);
                    hn2[rr][p*2]   = z0*hqr[rr][p*2]   + (1.f - z0)*hh0;
                    hn2[rr][p*2+1] = z1*hqr[rr][p*2+1] + (1.f - z1)*hh1;
                }
            }
            #pragma unroll
            for (int rr = 0; rr < 2; rr++)
                #pragma unroll
                for (int i = 0; i < 4; i++) hqr[rr][i] = hn2[rr][i];
            mb_wait(mFREE, par);
            ull q00 = pk2(hn2[0][0], hn2[0][1]), q01 = pk2(hn2[0][2], hn2[0][3]);
            ull q10 = pk2(hn2[1][0], hn2[1][1]), q11 = pk2(hn2[1][2], hn2[1][3]);
            #pragma unroll
            for (int rk = 0; rk < CL; rk++) {
                uint32_t p0 = map2[rk];
                st_rem64(p0, q00); st_rem64(p0 + 8, q01);
                uint32_t p1 = p0 + (uint32_t)(H2S*4);
                st_rem64(p1, q10); st_rem64(p1 + 8, q11);
            }
            __syncwarp();
            if (tid < 8) mb_post(mRDY2, (uint32_t)tid);
        }
    }
    mb_wait(mRDY2, (uint32_t)((T - 1) & 1));

    if (c == 0) {
        float* sD3 = sm + OFF_SC;
        float* sD4 = sm + OFF_SC + Br*64;
        __syncthreads();
        for (int i = tid; i < Br*64; i += NTHR) {
            int r = i >> 6, o = i & 63;
            float a = b3[o];
            #pragma unroll 8
            for (int k = 0; k < 128; k++) a += sm[OFF_H2 + r*H2S + k] * w3[k*64 + o];
            sD3[i] = a;
        }
        __syncthreads();
        for (int i = tid; i < Br*32; i += NTHR) {
            int r = i >> 5, o = i & 31;
            float a = b4[o];
            #pragma unroll 8
            for (int k = 0; k < 64; k++) a += sD3[r*64 + k] * w4[k*32 + o];
            sD4[i] = a;
        }
        __syncthreads();
        for (int i = tid; i < Br*OUTW; i += NTHR) {
            int r = i / OUTW, o = i % OUTW;
            float a = b5[o];
            #pragma unroll 8
            for (int k = 0; k < 32; k++) a += sD4[r*32 + k] * w5[k*OUTW + o];
            out[(g*Br + r)*OUTW + o] = a;
        }
    }
}

extern "C" void kernel_launch(void* const* d_in, const int* in_sizes, int n_in,
                              void* d_out, int out_size) {
    (void)in_sizes; (void)n_in; (void)out_size;
    const float* x  = (const float*)d_in[0];
    const float* k1 = (const float*)d_in[1];
    const float* r1 = (const float*)d_in[2];
    const float* b1 = (const float*)d_in[3];
    const float* k2 = (const float*)d_in[4];
    const float* r2 = (const float*)d_in[5];
    const float* b2 = (const float*)d_in[6];
    const float* w3 = (const float*)d_in[7];
    const float* b3 = (const float*)d_in[8];
    const float* w4 = (const float*)d_in[9];
    const float* b4 = (const float*)d_in[10];
    const float* w5 = (const float*)d_in[11];
    const float* b5 = (const float*)d_in[12];
    float* out = (float*)d_out;
    cudaFuncSetAttribute(gru_stack_kernel,
                         cudaFuncAttributeMaxDynamicSharedMemorySize, (int)SMEM_BYTES);
    gru_stack_kernel<<<128, NTHR, SMEM_BYTES>>>(
        x, k1, r1, b1, k2, r2, b2, w3, b3, w4, b4, w5, b5, out);
}